// round 6
// baseline (speedup 1.0000x reference)
#include <cuda_runtime.h>

#define N 8192
#define H 512
#define SCALE 0.044194173824159216f   // 1/sqrt(512)
#define SHIFT 50.0f

// Scratch (device globals; no allocation allowed)
__device__ float g_khT[H * N];    // kh transposed: [h][node] (original order)
__device__ float g_vh[N * H];     // vh row-major (original order)
__device__ float g_khTs[H * N];   // kh transposed, sorted node order
__device__ float g_vhp[N * H];    // vh row-major, sorted node order
__device__ int   g_bucket[N];
__device__ int   g_perm[N];
__device__ int   g_bsorted[N];
__device__ int   g_chist[32 * 4];
__device__ int   g_bstart[5];

// ---------------------------------------------------------------------------
// Producer: kh = X@kW (stored transposed), vh = X@vW (row-major)
// ---------------------------------------------------------------------------
__global__ __launch_bounds__(128) void producer_kernel(const float* __restrict__ A,
                                                       const float* __restrict__ kW,
                                                       const float* __restrict__ vW) {
    const float* B = blockIdx.z ? vW : kW;
    __shared__ float At[16][64];
    __shared__ float Bt[16][128];
    int t = threadIdx.x;
    int tx = t & 15, ty = t >> 4;
    int r0 = blockIdx.x * 64, c0 = blockIdx.y * 128;

    float acc[8][8];
#pragma unroll
    for (int i = 0; i < 8; i++)
#pragma unroll
        for (int j = 0; j < 8; j++) acc[i][j] = 0.f;

    for (int kk = 0; kk < H; kk += 16) {
#pragma unroll
        for (int x = 0; x < 2; x++) {
            int fid = t + x * 128;
            int r = fid >> 2, c4 = fid & 3;
            float4 v = *(const float4*)&A[(r0 + r) * H + kk + c4 * 4];
            At[c4 * 4 + 0][r] = v.x; At[c4 * 4 + 1][r] = v.y;
            At[c4 * 4 + 2][r] = v.z; At[c4 * 4 + 3][r] = v.w;
        }
#pragma unroll
        for (int x = 0; x < 4; x++) {
            int fid = t + x * 128;
            int k = fid >> 5, cv = fid & 31;
            *(float4*)&Bt[k][cv * 4] = *(const float4*)&B[(kk + k) * 512 + c0 + cv * 4];
        }
        __syncthreads();
#pragma unroll
        for (int k = 0; k < 16; k++) {
            float a[8], b[8];
            *(float4*)(a)     = *(float4*)&At[k][ty * 8];
            *(float4*)(a + 4) = *(float4*)&At[k][ty * 8 + 4];
            *(float4*)(b)     = *(float4*)&Bt[k][tx * 8];
            *(float4*)(b + 4) = *(float4*)&Bt[k][tx * 8 + 4];
#pragma unroll
            for (int i = 0; i < 8; i++)
#pragma unroll
                for (int j = 0; j < 8; j++) acc[i][j] = fmaf(a[i], b[j], acc[i][j]);
        }
        __syncthreads();
    }

    if (blockIdx.z == 0) {
#pragma unroll
        for (int i = 0; i < 8; i++)
#pragma unroll
            for (int j = 0; j < 8; j++)
                g_khT[(c0 + tx * 8 + j) * N + r0 + ty * 8 + i] = acc[i][j];
    } else {
#pragma unroll
        for (int i = 0; i < 8; i++) {
            int base = (r0 + ty * 8 + i) * H + c0 + tx * 8;
            *(float4*)&g_vh[base]     = make_float4(acc[i][0], acc[i][1], acc[i][2], acc[i][3]);
            *(float4*)&g_vh[base + 4] = make_float4(acc[i][4], acc[i][5], acc[i][6], acc[i][7]);
        }
    }
}

// ---------------------------------------------------------------------------
__global__ void bucket_kernel(const float* __restrict__ rot) {
    int n = blockIdx.x * 256 + threadIdx.x;
    float v0 = 0.f, v1 = 0.f;
#pragma unroll 8
    for (int h = 0; h < H; h++) {
        float k = g_khT[h * N + n];
        v0 = fmaf(k, rot[h * 2 + 0], v0);
        v1 = fmaf(k, rot[h * 2 + 1], v1);
    }
    float best = v0; int b = 0;
    if (v1  > best) { best = v1;  b = 1; }
    if (-v0 > best) { best = -v0; b = 2; }
    if (-v1 > best) {             b = 3; }
    g_bucket[n] = b;
}

// ---------------------------------------------------------------------------
// Stable counting sort by bucket (deterministic)
// ---------------------------------------------------------------------------
__global__ void hist_kernel() {
    __shared__ int h[4];
    int t = threadIdx.x;
    if (t < 4) h[t] = 0;
    __syncthreads();
    atomicAdd(&h[g_bucket[blockIdx.x * 256 + t]], 1);
    __syncthreads();
    if (t < 4) g_chist[blockIdx.x * 4 + t] = h[t];
}

__global__ void scatter_kernel() {
    __shared__ int lb[256];
    __shared__ int chs[128];
    int t = threadIdx.x, c = blockIdx.x;
    int node = c * 256 + t;
    int b = g_bucket[node];
    lb[t] = b;
    if (t < 128) chs[t] = g_chist[t];
    __syncthreads();

    int tot[4] = {0, 0, 0, 0};
    int pri = 0;
    for (int cc = 0; cc < 32; cc++) {
        if (cc < c) pri += chs[cc * 4 + b];
        tot[0] += chs[cc * 4 + 0]; tot[1] += chs[cc * 4 + 1];
        tot[2] += chs[cc * 4 + 2]; tot[3] += chs[cc * 4 + 3];
    }
    int bs = 0;
    for (int bb = 0; bb < 4; bb++) if (bb < b) bs += tot[bb];
    int r = 0;
    for (int j = 0; j < t; j++) r += (lb[j] == b);
    int pos = bs + pri + r;
    g_perm[pos] = node;
    g_bsorted[pos] = b;

    if (c == 0 && t < 4) {
        int s = 0;
        for (int bb = 0; bb < t; bb++) s += tot[bb];
        g_bstart[t] = s;
        if (t == 0) g_bstart[4] = N;
    }
}

// ---------------------------------------------------------------------------
__global__ void permute_khT_kernel() {
    int idx = blockIdx.x * 256 + threadIdx.x;
    int h = idx >> 13, pos = idx & 8191;
    g_khTs[idx] = g_khT[(h << 13) + g_perm[pos]];
}

__global__ void permute_vh_kernel() {
    int idx = blockIdx.x * 256 + threadIdx.x;
    int pos = idx >> 7, c4 = idx & 127;
    ((float4*)g_vhp)[idx] = ((const float4*)g_vh)[g_perm[pos] * 128 + c4];
}

// ---------------------------------------------------------------------------
// Fused block-diagonal attention, sorted order.
// 256 threads. GEMM1: BK=32 double-buffered with register staging.
// GEMM2: hp chunks of 64 H-cols, full-height 128x68 V tile; per-thread
// 2 rows x 8 cols with tx8 in [0,8) -> exact 64-col cover (R5 bug fix).
// ---------------------------------------------------------------------------
#define NCH 16          // H / 32 k-chunks
__global__ __launch_bounds__(256) void attn_kernel(const int* __restrict__ adj,
                                                   float* __restrict__ out) {
    extern __shared__ float sm[];
    float* Os   = sm;                   // [64][520]
    float* Ps   = Os + 64 * 520;        // [64][132]
    float* ovl  = Ps + 64 * 132;        // 12288 floats: Qt/Kt x2 | Vs[128][68]
    float* lrow = ovl + 12288;          // [64]
    int*   br   = (int*)(lrow + 64);    // [64]
    int*   pr   = br + 64;              // [64]
    int*   bc   = pr + 64;              // [128]
    int*   pc   = bc + 128;             // [128]
    float* Vs   = ovl;

    int t = threadIdx.x;
    int tx = t & 15, ty = t >> 4;       // GEMM1 mapping: 16 x 16
    int tx8 = t & 7, ty8 = t >> 3;      // GEMM2 mapping: 8 x 32
    int row0 = blockIdx.x * 64;

    for (int i = t; i < 64 * 520; i += 256) Os[i] = 0.f;
    if (t < 64) {
        lrow[t] = 0.f;
        br[t] = g_bsorted[row0 + t];
        pr[t] = g_perm[row0 + t];
    }
    __syncthreads();

    int rb[4], rowbase[4];
#pragma unroll
    for (int i = 0; i < 4; i++) {
        rb[i] = br[ty * 4 + i];
        rowbase[i] = pr[ty * 4 + i] * N;
    }

    int cstart = g_bstart[br[0]];
    int cend   = g_bstart[br[63] + 1];

    // per-thread GEMM1 load geometry
    int qk = t >> 4, qr = (t & 15) * 4;   // Qt rows qk, qk+16
    int kt = t >> 5, kc = (t & 31) * 4;   // Kt rows kt, +8, +16, +24

    for (int col0 = cstart & ~127; col0 < cend; col0 += 128) {
        if (t < 128) {
            bc[t] = g_bsorted[col0 + t];
            pc[t] = g_perm[col0 + t];
        }
        __syncthreads();

        // ---- prefetch adj + bucket cols into regs (consumed after GEMM1) ----
        int cb[8], cg[8];
#pragma unroll
        for (int j = 0; j < 8; j++) {
            int cidx = (j < 4) ? (tx * 4 + j) : (64 + tx * 4 + j - 4);
            cb[j] = bc[cidx];
            cg[j] = pc[cidx];
        }
        int adjv[4][8];
#pragma unroll
        for (int i = 0; i < 4; i++)
#pragma unroll
            for (int j = 0; j < 8; j++)
                adjv[i][j] = __ldg(&adj[rowbase[i] + cg[j]]);

        // ---- GEMM1: S[64x128] = Q @ K^T, BK=32 double-buffered ----
        float s[4][8];
#pragma unroll
        for (int i = 0; i < 4; i++)
#pragma unroll
            for (int j = 0; j < 8; j++) s[i][j] = 0.f;

        float4 q0, q1, k0, k1, k2, k3;
        {   // preload chunk 0
            const float* p = g_khTs;
            q0 = *(const float4*)&p[(qk) * N + row0 + qr];
            q1 = *(const float4*)&p[(qk + 16) * N + row0 + qr];
            k0 = *(const float4*)&p[(kt) * N + col0 + kc];
            k1 = *(const float4*)&p[(kt + 8) * N + col0 + kc];
            k2 = *(const float4*)&p[(kt + 16) * N + col0 + kc];
            k3 = *(const float4*)&p[(kt + 24) * N + col0 + kc];
            float* Qb = ovl; float* Kb = ovl + 2048;
            *(float4*)&Qb[qk * 64 + qr]        = q0;
            *(float4*)&Qb[(qk + 16) * 64 + qr] = q1;
            *(float4*)&Kb[kt * 128 + kc]        = k0;
            *(float4*)&Kb[(kt + 8) * 128 + kc]  = k1;
            *(float4*)&Kb[(kt + 16) * 128 + kc] = k2;
            *(float4*)&Kb[(kt + 24) * 128 + kc] = k3;
        }
        __syncthreads();

#pragma unroll 1
        for (int c = 0; c < NCH; c++) {
            if (c + 1 < NCH) {
                int kk = (c + 1) * 32;
                const float* p = g_khTs;
                q0 = *(const float4*)&p[(kk + qk) * N + row0 + qr];
                q1 = *(const float4*)&p[(kk + qk + 16) * N + row0 + qr];
                k0 = *(const float4*)&p[(kk + kt) * N + col0 + kc];
                k1 = *(const float4*)&p[(kk + kt + 8) * N + col0 + kc];
                k2 = *(const float4*)&p[(kk + kt + 16) * N + col0 + kc];
                k3 = *(const float4*)&p[(kk + kt + 24) * N + col0 + kc];
            }
            {
                float* Qb = ovl + (c & 1) * 6144;
                float* Kb = Qb + 2048;
#pragma unroll 8
                for (int k = 0; k < 32; k++) {
                    float a[4], b[8];
                    *(float4*)(a)     = *(float4*)&Qb[k * 64 + ty * 4];
                    *(float4*)(b)     = *(float4*)&Kb[k * 128 + tx * 4];
                    *(float4*)(b + 4) = *(float4*)&Kb[k * 128 + 64 + tx * 4];
#pragma unroll
                    for (int i = 0; i < 4; i++)
#pragma unroll
                        for (int j = 0; j < 8; j++) s[i][j] = fmaf(a[i], b[j], s[i][j]);
                }
            }
            if (c + 1 < NCH) {
                float* Qb = ovl + ((c + 1) & 1) * 6144;
                float* Kb = Qb + 2048;
                *(float4*)&Qb[qk * 64 + qr]        = q0;
                *(float4*)&Qb[(qk + 16) * 64 + qr] = q1;
                *(float4*)&Kb[kt * 128 + kc]        = k0;
                *(float4*)&Kb[(kt + 8) * 128 + kc]  = k1;
                *(float4*)&Kb[(kt + 16) * 128 + kc] = k2;
                *(float4*)&Kb[(kt + 24) * 128 + kc] = k3;
                __syncthreads();
            }
        }

        // ---- mask + exp -> Ps ----
#pragma unroll
        for (int i = 0; i < 4; i++) {
            float p[8];
#pragma unroll
            for (int j = 0; j < 8; j++) {
                bool valid = (rb[i] == cb[j]) && (adjv[i][j] > 0);
                p[j] = valid ? __expf(fmaf(s[i][j], SCALE, -SHIFT)) : 0.f;
            }
            int base = (ty * 4 + i) * 132;
            *(float4*)&Ps[base + tx * 4]      = make_float4(p[0], p[1], p[2], p[3]);
            *(float4*)&Ps[base + 64 + tx * 4] = make_float4(p[4], p[5], p[6], p[7]);
        }
        __syncthreads();

        // ---- row-sum of p into l ----
        if (t < 64) {
            float acc = 0.f;
#pragma unroll 8
            for (int j = 0; j < 128; j++) acc += Ps[t * 132 + j];
            lrow[t] += acc;
        }

        // ---- GEMM2: O[64x512] += P[64x128] @ V[128x512], hp = 64-col chunks
        //      per-thread 2 rows x 8 cols; tx8 in [0,8): cols {tx8*4, 32+tx8*4}
#pragma unroll 1
        for (int hp = 0; hp < 8; hp++) {
            __syncthreads();   // previous hp compute (or GEMM1/rowsum) fully done
#pragma unroll
            for (int x = 0; x < 8; x++) {
                int fid = t + x * 256;
                int r = fid >> 4, c4 = (fid & 15) * 4;
                *(float4*)&Vs[r * 68 + c4] =
                    *(const float4*)&g_vhp[(col0 + r) * H + hp * 64 + c4];
            }
            __syncthreads();

            float c[2][8];
#pragma unroll
            for (int i = 0; i < 2; i++) {
                int base = (ty8 * 2 + i) * 520 + hp * 64;
                *(float4*)&c[i][0] = *(float4*)&Os[base + tx8 * 4];
                *(float4*)&c[i][4] = *(float4*)&Os[base + 32 + tx8 * 4];
            }
#pragma unroll 8
            for (int k = 0; k < 128; k++) {
                float b[8];
                *(float4*)&b[0] = *(float4*)&Vs[k * 68 + tx8 * 4];
                *(float4*)&b[4] = *(float4*)&Vs[k * 68 + 32 + tx8 * 4];
                float a0 = Ps[(ty8 * 2 + 0) * 132 + k];
                float a1 = Ps[(ty8 * 2 + 1) * 132 + k];
#pragma unroll
                for (int j = 0; j < 8; j++) {
                    c[0][j] = fmaf(a0, b[j], c[0][j]);
                    c[1][j] = fmaf(a1, b[j], c[1][j]);
                }
            }
#pragma unroll
            for (int i = 0; i < 2; i++) {
                int base = (ty8 * 2 + i) * 520 + hp * 64;
                *(float4*)&Os[base + tx8 * 4]      = *(float4*)&c[i][0];
                *(float4*)&Os[base + 32 + tx8 * 4] = *(float4*)&c[i][4];
            }
        }
        __syncthreads();
    }

    // ---- epilogue: normalize + ELU + scatter rows to original order ----
#pragma unroll 1
    for (int x = 0; x < 32; x++) {
        int fid = t + x * 256;
        int r = fid >> 7, cv = fid & 127;
        float inv = 1.f / lrow[r];
        float4 v = *(float4*)&Os[r * 520 + cv * 4];
        v.x *= inv; v.y *= inv; v.z *= inv; v.w *= inv;
        v.x = v.x > 0.f ? v.x : expm1f(v.x);
        v.y = v.y > 0.f ? v.y : expm1f(v.y);
        v.z = v.z > 0.f ? v.z : expm1f(v.z);
        v.w = v.w > 0.f ? v.w : expm1f(v.w);
        *(float4*)&out[pr[r] * H + cv * 4] = v;
    }
}

// ---------------------------------------------------------------------------
extern "C" void kernel_launch(void* const* d_in, const int* in_sizes, int n_in,
                              void* d_out, int out_size) {
    const float* input = (const float*)d_in[0];
    const int*   adj   = (const int*)d_in[1];
    const float* rot   = (const float*)d_in[2];
    const float* kW    = (const float*)d_in[3];
    const float* vW    = (const float*)d_in[4];
    float* out = (float*)d_out;

    const int smem_bytes = (64 * 520 + 64 * 132 + 12288 + 64) * 4
                         + (64 + 64 + 128 + 128) * 4;
    cudaFuncSetAttribute(attn_kernel, cudaFuncAttributeMaxDynamicSharedMemorySize,
                         smem_bytes);

    producer_kernel<<<dim3(N / 64, H / 128, 2), 128>>>(input, kW, vW);
    bucket_kernel<<<N / 256, 256>>>(rot);
    hist_kernel<<<32, 256>>>();
    scatter_kernel<<<32, 256>>>();
    permute_khT_kernel<<<H * N / 256, 256>>>();
    permute_vh_kernel<<<N * 128 / 256, 256>>>();
    attn_kernel<<<N / 64, 256, smem_bytes>>>(adj, out);
}

// round 8
// speedup vs baseline: 2.0098x; 2.0098x over previous
#include <cuda_runtime.h>
#include <cuda_bf16.h>
#include <cstdint>

#define N 8192
#define H 512
#define SCALE 0.044194173824159216f   // 1/sqrt(512)
#define SHIFT 50.0f

// ---------------- global scratch (no allocation allowed) -------------------
__device__ float g_khT[H * N];        // kh [h][node], original order
__device__ float g_kh [N * H];        // kh row-major, original order
__device__ float g_vh [N * H];        // vh row-major, original order
__device__ int   g_bucket[N];
__device__ int   g_perm[N];
__device__ int   g_bsorted[N];
__device__ int   g_chist[32 * 4];
__device__ int   g_bstart[5];
__device__ __nv_bfloat16 g_khb_hi[N * H];   // kh sorted, row-major [pos][h]
__device__ __nv_bfloat16 g_khb_lo[N * H];
__device__ __nv_bfloat16 g_vT_hi[H * N];    // vh^T sorted: [h][pos]
__device__ __nv_bfloat16 g_vT_lo[H * N];

// ---------------- mma.sync m16n8k16 bf16 -> f32 ----------------------------
__device__ __forceinline__ void mma16816(float* c, const uint32_t* a,
                                         uint32_t b0, uint32_t b1) {
    asm volatile(
        "mma.sync.aligned.m16n8k16.row.col.f32.bf16.bf16.f32 "
        "{%0,%1,%2,%3}, {%4,%5,%6,%7}, {%8,%9}, {%0,%1,%2,%3};"
        : "+f"(c[0]), "+f"(c[1]), "+f"(c[2]), "+f"(c[3])
        : "r"(a[0]), "r"(a[1]), "r"(a[2]), "r"(a[3]), "r"(b0), "r"(b1));
}
__device__ __forceinline__ uint32_t packbf(float x, float y) {
    __nv_bfloat16 hx = __float2bfloat16(x), hy = __float2bfloat16(y);
    return (uint32_t)__bfloat16_as_ushort(hx) |
           ((uint32_t)__bfloat16_as_ushort(hy) << 16);
}

// ---------------------------------------------------------------------------
// Producer: kh = X@kW (khT + kh row-major), vh = X@vW (row-major)
// ---------------------------------------------------------------------------
__global__ __launch_bounds__(128) void producer_kernel(const float* __restrict__ A,
                                                       const float* __restrict__ kW,
                                                       const float* __restrict__ vW) {
    const float* B = blockIdx.z ? vW : kW;
    __shared__ float At[16][64];
    __shared__ float Bt[16][128];
    int t = threadIdx.x;
    int tx = t & 15, ty = t >> 4;
    int r0 = blockIdx.x * 64, c0 = blockIdx.y * 128;

    float acc[8][8];
#pragma unroll
    for (int i = 0; i < 8; i++)
#pragma unroll
        for (int j = 0; j < 8; j++) acc[i][j] = 0.f;

    for (int kk = 0; kk < H; kk += 16) {
#pragma unroll
        for (int x = 0; x < 2; x++) {
            int fid = t + x * 128;
            int r = fid >> 2, c4 = fid & 3;
            float4 v = *(const float4*)&A[(r0 + r) * H + kk + c4 * 4];
            At[c4 * 4 + 0][r] = v.x; At[c4 * 4 + 1][r] = v.y;
            At[c4 * 4 + 2][r] = v.z; At[c4 * 4 + 3][r] = v.w;
        }
#pragma unroll
        for (int x = 0; x < 4; x++) {
            int fid = t + x * 128;
            int k = fid >> 5, cv = fid & 31;
            *(float4*)&Bt[k][cv * 4] = *(const float4*)&B[(kk + k) * 512 + c0 + cv * 4];
        }
        __syncthreads();
#pragma unroll
        for (int k = 0; k < 16; k++) {
            float a[8], b[8];
            *(float4*)(a)     = *(float4*)&At[k][ty * 8];
            *(float4*)(a + 4) = *(float4*)&At[k][ty * 8 + 4];
            *(float4*)(b)     = *(float4*)&Bt[k][tx * 8];
            *(float4*)(b + 4) = *(float4*)&Bt[k][tx * 8 + 4];
#pragma unroll
            for (int i = 0; i < 8; i++)
#pragma unroll
                for (int j = 0; j < 8; j++) acc[i][j] = fmaf(a[i], b[j], acc[i][j]);
        }
        __syncthreads();
    }

    if (blockIdx.z == 0) {
#pragma unroll
        for (int i = 0; i < 8; i++) {
#pragma unroll
            for (int j = 0; j < 8; j++)
                g_khT[(c0 + tx * 8 + j) * N + r0 + ty * 8 + i] = acc[i][j];
            int base = (r0 + ty * 8 + i) * H + c0 + tx * 8;
            *(float4*)&g_kh[base]     = make_float4(acc[i][0], acc[i][1], acc[i][2], acc[i][3]);
            *(float4*)&g_kh[base + 4] = make_float4(acc[i][4], acc[i][5], acc[i][6], acc[i][7]);
        }
    } else {
#pragma unroll
        for (int i = 0; i < 8; i++) {
            int base = (r0 + ty * 8 + i) * H + c0 + tx * 8;
            *(float4*)&g_vh[base]     = make_float4(acc[i][0], acc[i][1], acc[i][2], acc[i][3]);
            *(float4*)&g_vh[base + 4] = make_float4(acc[i][4], acc[i][5], acc[i][6], acc[i][7]);
        }
    }
}

// ---------------------------------------------------------------------------
__global__ void bucket_kernel(const float* __restrict__ rot) {
    int n = blockIdx.x * 256 + threadIdx.x;
    float v0 = 0.f, v1 = 0.f;
#pragma unroll 8
    for (int h = 0; h < H; h++) {
        float k = g_khT[h * N + n];
        v0 = fmaf(k, rot[h * 2 + 0], v0);
        v1 = fmaf(k, rot[h * 2 + 1], v1);
    }
    float best = v0; int b = 0;
    if (v1  > best) { best = v1;  b = 1; }
    if (-v0 > best) { best = -v0; b = 2; }
    if (-v1 > best) {             b = 3; }
    g_bucket[n] = b;
}

__global__ void hist_kernel() {
    __shared__ int h[4];
    int t = threadIdx.x;
    if (t < 4) h[t] = 0;
    __syncthreads();
    atomicAdd(&h[g_bucket[blockIdx.x * 256 + t]], 1);
    __syncthreads();
    if (t < 4) g_chist[blockIdx.x * 4 + t] = h[t];
}

__global__ void scatter_kernel() {
    __shared__ int lb[256];
    __shared__ int chs[128];
    int t = threadIdx.x, c = blockIdx.x;
    int node = c * 256 + t;
    int b = g_bucket[node];
    lb[t] = b;
    if (t < 128) chs[t] = g_chist[t];
    __syncthreads();

    int tot[4] = {0, 0, 0, 0};
    int pri = 0;
    for (int cc = 0; cc < 32; cc++) {
        if (cc < c) pri += chs[cc * 4 + b];
        tot[0] += chs[cc * 4 + 0]; tot[1] += chs[cc * 4 + 1];
        tot[2] += chs[cc * 4 + 2]; tot[3] += chs[cc * 4 + 3];
    }
    int bs = 0;
    for (int bb = 0; bb < 4; bb++) if (bb < b) bs += tot[bb];
    int r = 0;
    for (int j = 0; j < t; j++) r += (lb[j] == b);
    int pos = bs + pri + r;
    g_perm[pos] = node;
    g_bsorted[pos] = b;

    if (c == 0 && t < 4) {
        int s = 0;
        for (int bb = 0; bb < t; bb++) s += tot[bb];
        g_bstart[t] = s;
        if (t == 0) g_bstart[4] = N;
    }
}

// bf16 split converts (sorted order)
__global__ void conv_kh_kernel() {
    int idx = blockIdx.x * 256 + threadIdx.x;          // over N*H, h fastest
    int pos = idx >> 9, h = idx & 511;
    float v = g_kh[g_perm[pos] * H + h];
    __nv_bfloat16 hi = __float2bfloat16(v);
    g_khb_hi[idx] = hi;
    g_khb_lo[idx] = __float2bfloat16(v - __bfloat162float(hi));
}
__global__ void conv_vT_kernel() {
    int idx = blockIdx.x * 256 + threadIdx.x;          // over H*N, pos fastest
    int h = idx >> 13, pos = idx & 8191;
    float v = g_vh[g_perm[pos] * H + h];
    __nv_bfloat16 hi = __float2bfloat16(v);
    g_vT_hi[idx] = hi;
    g_vT_lo[idx] = __float2bfloat16(v - __bfloat162float(hi));
}

// ---------------------------------------------------------------------------
// Fused block-diagonal attention via mma.sync (HMMA), split-bf16 fp32 emu.
// CTA = 64 rows, 8 warps.  GEMM1: warp = 16 rows x 64 cols (S frags in regs,
// K-loop over 8 chunks of 64).  Mask+exp in-register -> P smem bf16 hi/lo.
// GEMM2: warp = 16 rows x 32 H-cols per 64-col chunk, O in smem fp32.
// ---------------------------------------------------------------------------
__global__ __launch_bounds__(256) void attn_kernel(const int* __restrict__ adj,
                                                   float* __restrict__ out) {
    extern __shared__ char sm[];
    float*          Os  = (float*)sm;                      // [64][520]
    __nv_bfloat16*  Phi = (__nv_bfloat16*)(sm + 133120);   // [64][136]
    __nv_bfloat16*  Plo = (__nv_bfloat16*)(sm + 150528);   // [64][136]
    __nv_bfloat16*  Qhi = (__nv_bfloat16*)(sm + 167936);   // [64][72]
    __nv_bfloat16*  Qlo = (__nv_bfloat16*)(sm + 177152);
    __nv_bfloat16*  Khi = (__nv_bfloat16*)(sm + 186368);   // [128][72]
    __nv_bfloat16*  Klo = (__nv_bfloat16*)(sm + 204800);
    __nv_bfloat16*  Vhi = (__nv_bfloat16*)(sm + 167936);   // overlay: [64][136]
    __nv_bfloat16*  Vlo = (__nv_bfloat16*)(sm + 185344);
    int*      bc  = (int*)(sm + 223232);                   // [128]
    int*      pc  = (int*)(sm + 223744);                   // [128]
    int*      pr  = (int*)(sm + 224256);                   // [64]
    int*      brr = (int*)(sm + 224512);                   // [64]
    uint32_t* mw  = (uint32_t*)(sm + 224768);              // [64][4]
    float*    lrh = (float*)(sm + 225792);                 // [2][64]

    int t = threadIdx.x, w = t >> 5, lane = t & 31;
    int g = lane >> 2, tig = lane & 3;
    int rb16 = (w & 3) * 16;          // warp row block
    int ch   = w >> 2;                // GEMM1 col half (0/1)
    int row0 = blockIdx.x * 64;

    for (int i = t; i < 64 * 520; i += 256) Os[i] = 0.f;
    if (t < 64) { pr[t] = g_perm[row0 + t]; brr[t] = g_bsorted[row0 + t]; }
    __syncthreads();

    int cstart = g_bstart[brr[0]];
    int cend   = g_bstart[brr[63] + 1];
    int cbase0 = cstart & ~127;
    float lsum0 = 0.f, lsum1 = 0.f;
    int r0w = rb16 + g, r1w = rb16 + g + 8;

    for (int col0 = cbase0; col0 < cend; col0 += 128) {
        __syncthreads();
        if (t < 128) { bc[t] = g_bsorted[col0 + t]; pc[t] = g_perm[col0 + t]; }
        __syncthreads();

        // ---- mask bitwords: row (t>>2), word (t&3); 32 adj gathers each ----
        {
            int r = t >> 2, wb = t & 3;
            const int* arow = adj + (size_t)pr[r] * N;
            int rbv = brr[r];
            uint32_t m = 0;
#pragma unroll
            for (int c = 0; c < 32; c++) {
                int ci = wb * 32 + c;
                if ((bc[ci] == rbv) && (arow[pc[ci]] > 0)) m |= (1u << c);
            }
            mw[t] = m;
        }

        // ---- GEMM1: S[64x128] = Q K^T, K = 512, chunks of 64 ----
        float sf[8][4];
#pragma unroll
        for (int nb = 0; nb < 8; nb++)
#pragma unroll
            for (int i = 0; i < 4; i++) sf[nb][i] = 0.f;

        for (int kk = 0; kk < 8; kk++) {
            __syncthreads();
#pragma unroll
            for (int x = 0; x < 2; x++) {    // Q: 64x64, 512 uint4 per array
                int fid = t + x * 256;
                int r = fid >> 3, c8 = (fid & 7) * 8;
                *(uint4*)&Qhi[r * 72 + c8] =
                    *(const uint4*)&g_khb_hi[(size_t)(row0 + r) * H + kk * 64 + c8];
                *(uint4*)&Qlo[r * 72 + c8] =
                    *(const uint4*)&g_khb_lo[(size_t)(row0 + r) * H + kk * 64 + c8];
            }
#pragma unroll
            for (int x = 0; x < 4; x++) {    // K: 128x64
                int fid = t + x * 256;
                int r = fid >> 3, c8 = (fid & 7) * 8;
                *(uint4*)&Khi[r * 72 + c8] =
                    *(const uint4*)&g_khb_hi[(size_t)(col0 + r) * H + kk * 64 + c8];
                *(uint4*)&Klo[r * 72 + c8] =
                    *(const uint4*)&g_khb_lo[(size_t)(col0 + r) * H + kk * 64 + c8];
            }
            __syncthreads();
#pragma unroll
            for (int ks = 0; ks < 4; ks++) {
                int kb = ks * 16 + 2 * tig;
                uint32_t ah[4], al[4];
                const __nv_bfloat16* q = &Qhi[r0w * 72 + kb];
                ah[0] = *(const uint32_t*)q;
                ah[1] = *(const uint32_t*)(q + 8 * 72);
                ah[2] = *(const uint32_t*)(q + 8);
                ah[3] = *(const uint32_t*)(q + 8 * 72 + 8);
                const __nv_bfloat16* ql = &Qlo[r0w * 72 + kb];
                al[0] = *(const uint32_t*)ql;
                al[1] = *(const uint32_t*)(ql + 8 * 72);
                al[2] = *(const uint32_t*)(ql + 8);
                al[3] = *(const uint32_t*)(ql + 8 * 72 + 8);
#pragma unroll
                for (int nb = 0; nb < 8; nb++) {
                    const __nv_bfloat16* kp = &Khi[(ch * 64 + nb * 8 + g) * 72 + kb];
                    uint32_t bh0 = *(const uint32_t*)kp;
                    uint32_t bh1 = *(const uint32_t*)(kp + 8);
                    const __nv_bfloat16* kl = &Klo[(ch * 64 + nb * 8 + g) * 72 + kb];
                    uint32_t bl0 = *(const uint32_t*)kl;
                    uint32_t bl1 = *(const uint32_t*)(kl + 8);
                    mma16816(sf[nb], ah, bh0, bh1);
                    mma16816(sf[nb], ah, bl0, bl1);
                    mma16816(sf[nb], al, bh0, bh1);
                }
            }
        }

        // ---- mask + exp in-register -> P smem (bf16 hi/lo) + lsum ----
#pragma unroll
        for (int nb = 0; nb < 8; nb++) {
            int col = ch * 64 + nb * 8 + 2 * tig;
            uint32_t m0 = mw[r0w * 4 + (col >> 5)];
            uint32_t m1 = mw[r1w * 4 + (col >> 5)];
            int bi = col & 31;
            float p00 = ((m0 >> bi) & 1)       ? __expf(fmaf(sf[nb][0], SCALE, -SHIFT)) : 0.f;
            float p01 = ((m0 >> (bi + 1)) & 1) ? __expf(fmaf(sf[nb][1], SCALE, -SHIFT)) : 0.f;
            float p10 = ((m1 >> bi) & 1)       ? __expf(fmaf(sf[nb][2], SCALE, -SHIFT)) : 0.f;
            float p11 = ((m1 >> (bi + 1)) & 1) ? __expf(fmaf(sf[nb][3], SCALE, -SHIFT)) : 0.f;
            lsum0 += p00 + p01;
            lsum1 += p10 + p11;
            *(uint32_t*)&Phi[r0w * 136 + col] = packbf(p00, p01);
            *(uint32_t*)&Phi[r1w * 136 + col] = packbf(p10, p11);
            float h00 = __bfloat162float(__float2bfloat16(p00));
            float h01 = __bfloat162float(__float2bfloat16(p01));
            float h10 = __bfloat162float(__float2bfloat16(p10));
            float h11 = __bfloat162float(__float2bfloat16(p11));
            *(uint32_t*)&Plo[r0w * 136 + col] = packbf(p00 - h00, p01 - h01);
            *(uint32_t*)&Plo[r1w * 136 + col] = packbf(p10 - h10, p11 - h11);
        }
        __syncthreads();   // P ready; K/Q reads done (V overlays them)

        // ---- GEMM2: O[64x512] += P[64x128] @ V[128x512], 8 chunks of 64 ----
        int ch2 = (w >> 2) * 32;       // 32 H-cols per warp within chunk
        for (int hc = 0; hc < 8; hc++) {
            if (hc) __syncthreads();
#pragma unroll
            for (int x = 0; x < 4; x++) {   // V: 64 hcols x 128 k
                int fid = t + x * 256;
                int r = fid >> 4, c8 = (fid & 15) * 8;
                *(uint4*)&Vhi[r * 136 + c8] =
                    *(const uint4*)&g_vT_hi[(size_t)(hc * 64 + r) * N + col0 + c8];
                *(uint4*)&Vlo[r * 136 + c8] =
                    *(const uint4*)&g_vT_lo[(size_t)(hc * 64 + r) * N + col0 + c8];
            }
            __syncthreads();

            float cf[4][4];
            int ob = r0w * 520 + hc * 64 + ch2;
#pragma unroll
            for (int nb = 0; nb < 4; nb++) {
                float2 v0 = *(float2*)&Os[ob + nb * 8 + 2 * tig];
                float2 v1 = *(float2*)&Os[ob + 8 * 520 + nb * 8 + 2 * tig];
                cf[nb][0] = v0.x; cf[nb][1] = v0.y;
                cf[nb][2] = v1.x; cf[nb][3] = v1.y;
            }
#pragma unroll
            for (int ks = 0; ks < 8; ks++) {
                int kb = ks * 16 + 2 * tig;
                uint32_t ah[4], al[4];
                const __nv_bfloat16* p = &Phi[r0w * 136 + kb];
                ah[0] = *(const uint32_t*)p;
                ah[1] = *(const uint32_t*)(p + 8 * 136);
                ah[2] = *(const uint32_t*)(p + 8);
                ah[3] = *(const uint32_t*)(p + 8 * 136 + 8);
                const __nv_bfloat16* pl = &Plo[r0w * 136 + kb];
                al[0] = *(const uint32_t*)pl;
                al[1] = *(const uint32_t*)(pl + 8 * 136);
                al[2] = *(const uint32_t*)(pl + 8);
                al[3] = *(const uint32_t*)(pl + 8 * 136 + 8);
#pragma unroll
                for (int nb = 0; nb < 4; nb++) {
                    const __nv_bfloat16* vp = &Vhi[(ch2 + nb * 8 + g) * 136 + kb];
                    uint32_t bh0 = *(const uint32_t*)vp;
                    uint32_t bh1 = *(const uint32_t*)(vp + 8);
                    const __nv_bfloat16* vl = &Vlo[(ch2 + nb * 8 + g) * 136 + kb];
                    uint32_t bl0 = *(const uint32_t*)vl;
                    uint32_t bl1 = *(const uint32_t*)(vl + 8);
                    mma16816(cf[nb], ah, bh0, bh1);
                    mma16816(cf[nb], ah, bl0, bl1);
                    mma16816(cf[nb], al, bh0, bh1);
                }
            }
#pragma unroll
            for (int nb = 0; nb < 4; nb++) {
                *(float2*)&Os[ob + nb * 8 + 2 * tig] = make_float2(cf[nb][0], cf[nb][1]);
                *(float2*)&Os[ob + 8 * 520 + nb * 8 + 2 * tig] = make_float2(cf[nb][2], cf[nb][3]);
            }
        }
    }

    // ---- lsum reduce (over tig) and publish ----
    lsum0 += __shfl_xor_sync(0xFFFFFFFFu, lsum0, 1);
    lsum0 += __shfl_xor_sync(0xFFFFFFFFu, lsum0, 2);
    lsum1 += __shfl_xor_sync(0xFFFFFFFFu, lsum1, 1);
    lsum1 += __shfl_xor_sync(0xFFFFFFFFu, lsum1, 2);
    if (tig == 0) {
        lrh[ch * 64 + r0w] = lsum0;
        lrh[ch * 64 + r1w] = lsum1;
    }
    __syncthreads();

    // ---- epilogue: normalize + ELU + scatter rows to original order ----
#pragma unroll 1
    for (int x = 0; x < 32; x++) {
        int fid = t + x * 256;
        int r = fid >> 7, c4 = fid & 127;
        float inv = 1.f / (lrh[r] + lrh[64 + r]);
        float4 v = *(float4*)&Os[r * 520 + c4 * 4];
        v.x *= inv; v.y *= inv; v.z *= inv; v.w *= inv;
        v.x = v.x > 0.f ? v.x : expm1f(v.x);
        v.y = v.y > 0.f ? v.y : expm1f(v.y);
        v.z = v.z > 0.f ? v.z : expm1f(v.z);
        v.w = v.w > 0.f ? v.w : expm1f(v.w);
        *(float4*)&out[(size_t)pr[r] * H + c4 * 4] = v;
    }
}

// ---------------------------------------------------------------------------
extern "C" void kernel_launch(void* const* d_in, const int* in_sizes, int n_in,
                              void* d_out, int out_size) {
    const float* input = (const float*)d_in[0];
    const int*   adj   = (const int*)d_in[1];
    const float* rot   = (const float*)d_in[2];
    const float* kW    = (const float*)d_in[3];
    const float* vW    = (const float*)d_in[4];
    float* out = (float*)d_out;

    const int smem_bytes = 226304;
    cudaFuncSetAttribute(attn_kernel, cudaFuncAttributeMaxDynamicSharedMemorySize,
                         smem_bytes);

    producer_kernel<<<dim3(N / 64, H / 128, 2), 128>>>(input, kW, vW);
    bucket_kernel<<<N / 256, 256>>>(rot);
    hist_kernel<<<32, 256>>>();
    scatter_kernel<<<32, 256>>>();
    conv_kh_kernel<<<(N * H) / 256, 256>>>();
    conv_vT_kernel<<<(H * N) / 256, 256>>>();
    attn_kernel<<<N / 64, 256, smem_bytes>>>(adj, out);
}

// round 11
// speedup vs baseline: 2.0501x; 1.0200x over previous
#include <cuda_runtime.h>
#include <cuda_bf16.h>
#include <cstdint>

#define N 8192
#define H 512
#define SCALE 0.044194173824159216f   // 1/sqrt(512)
#define SHIFT 50.0f

// ---------------- global scratch (no allocation allowed) -------------------
__device__ float g_khT[H * N];        // kh [h][node], original order
__device__ float g_kh [N * H];        // kh row-major, original order
__device__ float g_vh [N * H];        // vh row-major, original order
__device__ int   g_bucket[N];
__device__ int   g_perm[N];
__device__ int   g_bsorted[N];
__device__ int   g_chist[32 * 4];
__device__ int   g_bstart[5];
__device__ __nv_bfloat16 g_khb_hi[N * H];   // kh sorted, row-major [pos][h]
__device__ __nv_bfloat16 g_khb_lo[N * H];
__device__ __nv_bfloat16 g_vT_hi[H * N];    // vh^T sorted: [h][pos]
__device__ __nv_bfloat16 g_vT_lo[H * N];

// ---------------- mma.sync m16n8k16 bf16 -> f32 ----------------------------
__device__ __forceinline__ void mma16816(float* c, const uint32_t* a,
                                         uint32_t b0, uint32_t b1) {
    asm volatile(
        "mma.sync.aligned.m16n8k16.row.col.f32.bf16.bf16.f32 "
        "{%0,%1,%2,%3}, {%4,%5,%6,%7}, {%8,%9}, {%0,%1,%2,%3};"
        : "+f"(c[0]), "+f"(c[1]), "+f"(c[2]), "+f"(c[3])
        : "r"(a[0]), "r"(a[1]), "r"(a[2]), "r"(a[3]), "r"(b0), "r"(b1));
}
__device__ __forceinline__ uint32_t packbf(float x, float y) {
    __nv_bfloat16 hx = __float2bfloat16(x), hy = __float2bfloat16(y);
    return (uint32_t)__bfloat16_as_ushort(hx) |
           ((uint32_t)__bfloat16_as_ushort(hy) << 16);
}
#define CP16(dst, src) \
    asm volatile("cp.async.cg.shared.global [%0], [%1], 16;" :: "r"(dst), "l"(src))
#define CP_COMMIT() asm volatile("cp.async.commit_group;")
#define CP_WAIT0()  asm volatile("cp.async.wait_group 0;")

// ---------------------------------------------------------------------------
// Producer: kh = X@kW (khT + kh row-major), vh = X@vW (row-major)
// ---------------------------------------------------------------------------
__global__ __launch_bounds__(128) void producer_kernel(const float* __restrict__ A,
                                                       const float* __restrict__ kW,
                                                       const float* __restrict__ vW) {
    const float* B = blockIdx.z ? vW : kW;
    __shared__ float At[16][64];
    __shared__ float Bt[16][128];
    int t = threadIdx.x;
    int tx = t & 15, ty = t >> 4;
    int r0 = blockIdx.x * 64, c0 = blockIdx.y * 128;

    float acc[8][8];
#pragma unroll
    for (int i = 0; i < 8; i++)
#pragma unroll
        for (int j = 0; j < 8; j++) acc[i][j] = 0.f;

    for (int kk = 0; kk < H; kk += 16) {
#pragma unroll
        for (int x = 0; x < 2; x++) {
            int fid = t + x * 128;
            int r = fid >> 2, c4 = fid & 3;
            float4 v = *(const float4*)&A[(r0 + r) * H + kk + c4 * 4];
            At[c4 * 4 + 0][r] = v.x; At[c4 * 4 + 1][r] = v.y;
            At[c4 * 4 + 2][r] = v.z; At[c4 * 4 + 3][r] = v.w;
        }
#pragma unroll
        for (int x = 0; x < 4; x++) {
            int fid = t + x * 128;
            int k = fid >> 5, cv = fid & 31;
            *(float4*)&Bt[k][cv * 4] = *(const float4*)&B[(kk + k) * 512 + c0 + cv * 4];
        }
        __syncthreads();
#pragma unroll
        for (int k = 0; k < 16; k++) {
            float a[8], b[8];
            *(float4*)(a)     = *(float4*)&At[k][ty * 8];
            *(float4*)(a + 4) = *(float4*)&At[k][ty * 8 + 4];
            *(float4*)(b)     = *(float4*)&Bt[k][tx * 8];
            *(float4*)(b + 4) = *(float4*)&Bt[k][tx * 8 + 4];
#pragma unroll
            for (int i = 0; i < 8; i++)
#pragma unroll
                for (int j = 0; j < 8; j++) acc[i][j] = fmaf(a[i], b[j], acc[i][j]);
        }
        __syncthreads();
    }

    if (blockIdx.z == 0) {
#pragma unroll
        for (int i = 0; i < 8; i++) {
#pragma unroll
            for (int j = 0; j < 8; j++)
                g_khT[(c0 + tx * 8 + j) * N + r0 + ty * 8 + i] = acc[i][j];
            int base = (r0 + ty * 8 + i) * H + c0 + tx * 8;
            *(float4*)&g_kh[base]     = make_float4(acc[i][0], acc[i][1], acc[i][2], acc[i][3]);
            *(float4*)&g_kh[base + 4] = make_float4(acc[i][4], acc[i][5], acc[i][6], acc[i][7]);
        }
    } else {
#pragma unroll
        for (int i = 0; i < 8; i++) {
            int base = (r0 + ty * 8 + i) * H + c0 + tx * 8;
            *(float4*)&g_vh[base]     = make_float4(acc[i][0], acc[i][1], acc[i][2], acc[i][3]);
            *(float4*)&g_vh[base + 4] = make_float4(acc[i][4], acc[i][5], acc[i][6], acc[i][7]);
        }
    }
}

// ---------------------------------------------------------------------------
__global__ void bucket_kernel(const float* __restrict__ rot) {
    int n = blockIdx.x * 256 + threadIdx.x;
    float v0 = 0.f, v1 = 0.f;
#pragma unroll 8
    for (int h = 0; h < H; h++) {
        float k = g_khT[h * N + n];
        v0 = fmaf(k, rot[h * 2 + 0], v0);
        v1 = fmaf(k, rot[h * 2 + 1], v1);
    }
    float best = v0; int b = 0;
    if (v1  > best) { best = v1;  b = 1; }
    if (-v0 > best) { best = -v0; b = 2; }
    if (-v1 > best) {             b = 3; }
    g_bucket[n] = b;
}

__global__ void hist_kernel() {
    __shared__ int h[4];
    int t = threadIdx.x;
    if (t < 4) h[t] = 0;
    __syncthreads();
    atomicAdd(&h[g_bucket[blockIdx.x * 256 + t]], 1);
    __syncthreads();
    if (t < 4) g_chist[blockIdx.x * 4 + t] = h[t];
}

__global__ void scatter_kernel() {
    __shared__ int lb[256];
    __shared__ int chs[128];
    int t = threadIdx.x, c = blockIdx.x;
    int node = c * 256 + t;
    int b = g_bucket[node];
    lb[t] = b;
    if (t < 128) chs[t] = g_chist[t];
    __syncthreads();

    int tot[4] = {0, 0, 0, 0};
    int pri = 0;
    for (int cc = 0; cc < 32; cc++) {
        if (cc < c) pri += chs[cc * 4 + b];
        tot[0] += chs[cc * 4 + 0]; tot[1] += chs[cc * 4 + 1];
        tot[2] += chs[cc * 4 + 2]; tot[3] += chs[cc * 4 + 3];
    }
    int bs = 0;
    for (int bb = 0; bb < 4; bb++) if (bb < b) bs += tot[bb];
    int r = 0;
    for (int j = 0; j < t; j++) r += (lb[j] == b);
    int pos = bs + pri + r;
    g_perm[pos] = node;
    g_bsorted[pos] = b;

    if (c == 0 && t < 4) {
        int s = 0;
        for (int bb = 0; bb < t; bb++) s += tot[bb];
        g_bstart[t] = s;
        if (t == 0) g_bstart[4] = N;
    }
}

// bf16 split converts (sorted order)
__global__ void conv_kh_kernel() {
    int idx = blockIdx.x * 256 + threadIdx.x;          // over N*H, h fastest
    int pos = idx >> 9, h = idx & 511;
    float v = g_kh[g_perm[pos] * H + h];
    __nv_bfloat16 hi = __float2bfloat16(v);
    g_khb_hi[idx] = hi;
    g_khb_lo[idx] = __float2bfloat16(v - __bfloat162float(hi));
}
__global__ void conv_vT_kernel() {
    int idx = blockIdx.x * 256 + threadIdx.x;          // over H*N, pos fastest
    int h = idx >> 13, pos = idx & 8191;
    float v = g_vh[g_perm[pos] * H + h];
    __nv_bfloat16 hi = __float2bfloat16(v);
    g_vT_hi[idx] = hi;
    g_vT_lo[idx] = __float2bfloat16(v - __bfloat162float(hi));
}

// ---------------------------------------------------------------------------
// Fused block-diagonal attention via mma.sync, split-bf16, R8 numerics +
// cp.async depth-1 pipelines.
// GEMM1: 32 chunks of BK=16 (Q/K hi+lo, pitch 24 -> conflict-free frags).
// P stored hi+lo.  GEMM2: 16 chunks of 32 H-cols, V hi+lo double-buffered,
// A-frags (Phi/Plo) hoisted to registers once per col-tile.
// ---------------------------------------------------------------------------
__global__ __launch_bounds__(256) void attn_kernel(const int* __restrict__ adj,
                                                   float* __restrict__ out) {
    extern __shared__ char sm[];
    float*          Os  = (float*)sm;                      // [64][520] 133120B
    __nv_bfloat16*  Phi = (__nv_bfloat16*)(sm + 133120);   // [64][136] 17408B
    __nv_bfloat16*  Plo = (__nv_bfloat16*)(sm + 150528);   // [64][136] 17408B
    const int OVL = 167936;                                // 36864B staging
    // GEMM1 stage s (18432B): Qhi s*18432, Qlo +3072, Khi +6144, Klo +12288
    // GEMM2 stage s (17408B): Vhi s*17408, Vlo +8704
    int*      bc  = (int*)(sm + 204800);                   // [128]
    int*      pc  = (int*)(sm + 205312);                   // [128]
    int*      pr  = (int*)(sm + 205824);                   // [64]
    int*      brr = (int*)(sm + 206080);                   // [64]
    uint32_t* mw  = (uint32_t*)(sm + 206336);              // [64][4]
    float*    lrh = (float*)(sm + 207360);                 // [2][64]

    uint32_t sb = (uint32_t)__cvta_generic_to_shared(sm);
    int t = threadIdx.x, w = t >> 5, lane = t & 31;
    int g = lane >> 2, tig = lane & 3;
    int rb16 = (w & 3) * 16;          // warp row block
    int ch   = w >> 2;                // GEMM1 col half (0/1)
    int row0 = blockIdx.x * 64;

    for (int i = t; i < 64 * 520; i += 256) Os[i] = 0.f;
    if (t < 64) { pr[t] = g_perm[row0 + t]; brr[t] = g_bsorted[row0 + t]; }
    __syncthreads();

    int cstart = g_bstart[brr[0]];
    int cend   = g_bstart[brr[63] + 1];
    int cbase0 = cstart & ~127;
    float lsum0 = 0.f, lsum1 = 0.f;
    int r0w = rb16 + g, r1w = rb16 + g + 8;

    // cp.async per-thread mapping (GEMM1): Q: r=t>>2 (64), sub=t&3
    int qr = t >> 2, qs = t & 3;
    int qhl = qs >> 1, qseg = qs & 1;

    for (int col0 = cbase0; col0 < cend; col0 += 128) {
        __syncthreads();
        if (t < 128) { bc[t] = g_bsorted[col0 + t]; pc[t] = g_perm[col0 + t]; }
        __syncthreads();

        // ---- issue GEMM1 chunk 0 loads (overlap with adj gathers below) ----
        {
            uint32_t st = sb + OVL;
            const __nv_bfloat16* qsrc = qhl ? g_khb_lo : g_khb_hi;
            CP16(st + qhl * 3072 + qr * 48 + qseg * 16,
                 &qsrc[(size_t)(row0 + qr) * H + qseg * 8]);
#pragma unroll
            for (int x = 0; x < 2; x++) {
                int fid = t + x * 256;
                int r = fid >> 2, s2 = fid & 3;
                const __nv_bfloat16* ksrc = (s2 >> 1) ? g_khb_lo : g_khb_hi;
                CP16(st + 6144 + (s2 >> 1) * 6144 + r * 48 + (s2 & 1) * 16,
                     &ksrc[(size_t)(col0 + r) * H + (s2 & 1) * 8]);
            }
            CP_COMMIT();
        }

        // ---- mask bitwords: row (t>>2), word (t&3); 32 adj gathers each ----
        {
            int r = t >> 2, wb = t & 3;
            const int* arow = adj + (size_t)pr[r] * N;
            int rbv = brr[r];
            uint32_t m = 0;
#pragma unroll
            for (int c = 0; c < 32; c++) {
                int ci = wb * 32 + c;
                if ((bc[ci] == rbv) && (arow[pc[ci]] > 0)) m |= (1u << c);
            }
            mw[t] = m;
        }

        // ---- GEMM1: S[64x128] = Q K^T, 32 chunks of 16, depth-1 pipeline ----
        float sf[8][4];
#pragma unroll
        for (int nb = 0; nb < 8; nb++)
#pragma unroll
            for (int i = 0; i < 4; i++) sf[nb][i] = 0.f;

#pragma unroll 1
        for (int c = 0; c < 32; c++) {
            CP_WAIT0();
            __syncthreads();
            if (c + 1 < 32) {
                int kk = (c + 1) * 16;
                uint32_t st = sb + OVL + ((c + 1) & 1) * 18432;
                const __nv_bfloat16* qsrc = qhl ? g_khb_lo : g_khb_hi;
                CP16(st + qhl * 3072 + qr * 48 + qseg * 16,
                     &qsrc[(size_t)(row0 + qr) * H + kk + qseg * 8]);
#pragma unroll
                for (int x = 0; x < 2; x++) {
                    int fid = t + x * 256;
                    int r = fid >> 2, s2 = fid & 3;
                    const __nv_bfloat16* ksrc = (s2 >> 1) ? g_khb_lo : g_khb_hi;
                    CP16(st + 6144 + (s2 >> 1) * 6144 + r * 48 + (s2 & 1) * 16,
                         &ksrc[(size_t)(col0 + r) * H + kk + (s2 & 1) * 8]);
                }
                CP_COMMIT();
            }
            const __nv_bfloat16* Qh = (const __nv_bfloat16*)(sm + OVL + (c & 1) * 18432);
            const __nv_bfloat16* Ql = Qh + 1536;
            const __nv_bfloat16* Kh = Qh + 3072;
            const __nv_bfloat16* Kl = Qh + 6144;
            {
                int kb = 2 * tig;
                uint32_t ah[4], al[4];
                const __nv_bfloat16* q = &Qh[r0w * 24 + kb];
                ah[0] = *(const uint32_t*)q;
                ah[1] = *(const uint32_t*)(q + 8 * 24);
                ah[2] = *(const uint32_t*)(q + 8);
                ah[3] = *(const uint32_t*)(q + 8 * 24 + 8);
                const __nv_bfloat16* ql = &Ql[r0w * 24 + kb];
                al[0] = *(const uint32_t*)ql;
                al[1] = *(const uint32_t*)(ql + 8 * 24);
                al[2] = *(const uint32_t*)(ql + 8);
                al[3] = *(const uint32_t*)(ql + 8 * 24 + 8);
#pragma unroll
                for (int nb = 0; nb < 8; nb++) {
                    const __nv_bfloat16* kp = &Kh[(ch * 64 + nb * 8 + g) * 24 + kb];
                    uint32_t bh0 = *(const uint32_t*)kp;
                    uint32_t bh1 = *(const uint32_t*)(kp + 8);
                    const __nv_bfloat16* kl = &Kl[(ch * 64 + nb * 8 + g) * 24 + kb];
                    uint32_t bl0 = *(const uint32_t*)kl;
                    uint32_t bl1 = *(const uint32_t*)(kl + 8);
                    mma16816(sf[nb], ah, bh0, bh1);
                    mma16816(sf[nb], ah, bl0, bl1);
                    mma16816(sf[nb], al, bh0, bh1);
                }
            }
        }

        // ---- mask + exp in-register -> Phi/Plo + lsum ----
#pragma unroll
        for (int nb = 0; nb < 8; nb++) {
            int col = ch * 64 + nb * 8 + 2 * tig;
            uint32_t m0 = mw[r0w * 4 + (col >> 5)];
            uint32_t m1 = mw[r1w * 4 + (col >> 5)];
            int bi = col & 31;
            float p00 = ((m0 >> bi) & 1)       ? __expf(fmaf(sf[nb][0], SCALE, -SHIFT)) : 0.f;
            float p01 = ((m0 >> (bi + 1)) & 1) ? __expf(fmaf(sf[nb][1], SCALE, -SHIFT)) : 0.f;
            float p10 = ((m1 >> bi) & 1)       ? __expf(fmaf(sf[nb][2], SCALE, -SHIFT)) : 0.f;
            float p11 = ((m1 >> (bi + 1)) & 1) ? __expf(fmaf(sf[nb][3], SCALE, -SHIFT)) : 0.f;
            lsum0 += p00 + p01;
            lsum1 += p10 + p11;
            *(uint32_t*)&Phi[r0w * 136 + col] = packbf(p00, p01);
            *(uint32_t*)&Phi[r1w * 136 + col] = packbf(p10, p11);
            float h00 = __bfloat162float(__float2bfloat16(p00));
            float h01 = __bfloat162float(__float2bfloat16(p01));
            float h10 = __bfloat162float(__float2bfloat16(p10));
            float h11 = __bfloat162float(__float2bfloat16(p11));
            *(uint32_t*)&Plo[r0w * 136 + col] = packbf(p00 - h00, p01 - h01);
            *(uint32_t*)&Plo[r1w * 136 + col] = packbf(p10 - h10, p11 - h11);
        }
        __syncthreads();   // P ready; GEMM1 staging free for V

        // ---- issue V(hc=0); hoist A-frags (Phi/Plo) into registers ----
#pragma unroll
        for (int x = 0; x < 4; x++) {
            int fid = t + x * 256;
            int hl = fid >> 9, r = (fid >> 4) & 31, s = fid & 15;
            uint32_t st = sb + OVL + hl * 8704;
            const __nv_bfloat16* vsrc = hl ? g_vT_lo : g_vT_hi;
            CP16(st + r * 272 + s * 16, &vsrc[(size_t)r * N + col0 + s * 8]);
        }
        CP_COMMIT();

        uint32_t pa[8][4], pl[8][4];
#pragma unroll
        for (int ks = 0; ks < 8; ks++) {
            int kb = ks * 16 + 2 * tig;
            const __nv_bfloat16* p = &Phi[r0w * 136 + kb];
            pa[ks][0] = *(const uint32_t*)p;
            pa[ks][1] = *(const uint32_t*)(p + 8 * 136);
            pa[ks][2] = *(const uint32_t*)(p + 8);
            pa[ks][3] = *(const uint32_t*)(p + 8 * 136 + 8);
            const __nv_bfloat16* q = &Plo[r0w * 136 + kb];
            pl[ks][0] = *(const uint32_t*)q;
            pl[ks][1] = *(const uint32_t*)(q + 8 * 136);
            pl[ks][2] = *(const uint32_t*)(q + 8);
            pl[ks][3] = *(const uint32_t*)(q + 8 * 136 + 8);
        }

        // ---- GEMM2: O[64x512] += P @ V, 16 chunks of 32 H-cols ----
        int ch2 = (w >> 2) * 16;       // 16 H-cols per warp within chunk
#pragma unroll 1
        for (int hc = 0; hc < 16; hc++) {
            CP_WAIT0();
            __syncthreads();
            if (hc + 1 < 16) {
                uint32_t st = sb + OVL + ((hc + 1) & 1) * 17408;
#pragma unroll
                for (int x = 0; x < 4; x++) {
                    int fid = t + x * 256;
                    int hl = fid >> 9, r = (fid >> 4) & 31, s = fid & 15;
                    const __nv_bfloat16* vsrc = hl ? g_vT_lo : g_vT_hi;
                    CP16(st + hl * 8704 + r * 272 + s * 16,
                         &vsrc[(size_t)((hc + 1) * 32 + r) * N + col0 + s * 8]);
                }
                CP_COMMIT();
            }
            const __nv_bfloat16* Vh = (const __nv_bfloat16*)(sm + OVL + (hc & 1) * 17408);
            const __nv_bfloat16* Vl = Vh + 4352;

            float cf[2][4];
            int ob = r0w * 520 + hc * 32 + ch2;
#pragma unroll
            for (int nb = 0; nb < 2; nb++) {
                float2 v0 = *(float2*)&Os[ob + nb * 8 + 2 * tig];
                float2 v1 = *(float2*)&Os[ob + 8 * 520 + nb * 8 + 2 * tig];
                cf[nb][0] = v0.x; cf[nb][1] = v0.y;
                cf[nb][2] = v1.x; cf[nb][3] = v1.y;
            }
#pragma unroll
            for (int ks = 0; ks < 8; ks++) {
                int kb = ks * 16 + 2 * tig;
#pragma unroll
                for (int nb = 0; nb < 2; nb++) {
                    const __nv_bfloat16* vp = &Vh[(ch2 + nb * 8 + g) * 136 + kb];
                    uint32_t bh0 = *(const uint32_t*)vp;
                    uint32_t bh1 = *(const uint32_t*)(vp + 8);
                    const __nv_bfloat16* vl = &Vl[(ch2 + nb * 8 + g) * 136 + kb];
                    uint32_t bl0 = *(const uint32_t*)vl;
                    uint32_t bl1 = *(const uint32_t*)(vl + 8);
                    mma16816(cf[nb], pa[ks], bh0, bh1);
                    mma16816(cf[nb], pa[ks], bl0, bl1);
                    mma16816(cf[nb], pl[ks], bh0, bh1);
                }
            }
#pragma unroll
            for (int nb = 0; nb < 2; nb++) {
                *(float2*)&Os[ob + nb * 8 + 2 * tig] = make_float2(cf[nb][0], cf[nb][1]);
                *(float2*)&Os[ob + 8 * 520 + nb * 8 + 2 * tig] = make_float2(cf[nb][2], cf[nb][3]);
            }
        }
    }

    // ---- lsum reduce (over tig) and publish ----
    lsum0 += __shfl_xor_sync(0xFFFFFFFFu, lsum0, 1);
    lsum0 += __shfl_xor_sync(0xFFFFFFFFu, lsum0, 2);
    lsum1 += __shfl_xor_sync(0xFFFFFFFFu, lsum1, 1);
    lsum1 += __shfl_xor_sync(0xFFFFFFFFu, lsum1, 2);
    if (tig == 0) {
        lrh[ch * 64 + r0w] = lsum0;
        lrh[ch * 64 + r1w] = lsum1;
    }
    __syncthreads();

    // ---- epilogue: normalize + ELU + scatter rows to original order ----
#pragma unroll 1
    for (int x = 0; x < 32; x++) {
        int fid = t + x * 256;
        int r = fid >> 7, c4 = fid & 127;
        float inv = 1.f / (lrh[r] + lrh[64 + r]);
        float4 v = *(float4*)&Os[r * 520 + c4 * 4];
        v.x *= inv; v.y *= inv; v.z *= inv; v.w *= inv;
        v.x = v.x > 0.f ? v.x : expm1f(v.x);
        v.y = v.y > 0.f ? v.y : expm1f(v.y);
        v.z = v.z > 0.f ? v.z : expm1f(v.z);
        v.w = v.w > 0.f ? v.w : expm1f(v.w);
        *(float4*)&out[(size_t)pr[r] * H + c4 * 4] = v;
    }
}

// ---------------------------------------------------------------------------
extern "C" void kernel_launch(void* const* d_in, const int* in_sizes, int n_in,
                              void* d_out, int out_size) {
    const float* input = (const float*)d_in[0];
    const int*   adj   = (const int*)d_in[1];
    const float* rot   = (const float*)d_in[2];
    const float* kW    = (const float*)d_in[3];
    const float* vW    = (const float*)d_in[4];
    float* out = (float*)d_out;

    const int smem_bytes = 207872;
    cudaFuncSetAttribute(attn_kernel, cudaFuncAttributeMaxDynamicSharedMemorySize,
                         smem_bytes);

    producer_kernel<<<dim3(N / 64, H / 128, 2), 128>>>(input, kW, vW);
    bucket_kernel<<<N / 256, 256>>>(rot);
    hist_kernel<<<32, 256>>>();
    scatter_kernel<<<32, 256>>>();
    conv_kh_kernel<<<(N * H) / 256, 256>>>();
    conv_vT_kernel<<<(H * N) / 256, 256>>>();
    attn_kernel<<<N / 64, 256, smem_bytes>>>(adj, out);
}